// round 1
// baseline (speedup 1.0000x reference)
#include <cuda_runtime.h>

// Fused Mamba block: in_proj -> causal depthwise conv+SiLU -> x_proj ->
// softplus(delta) -> selective scan -> D skip -> SiLU gate -> folded
// (out_proj @ lin1 @ lin2) head. One thread per (sequence, channel).

#define SPB 4          // sequences per block
#define NTHREADS 256   // SPB * D_INNER
#define SEQ 64
#define DM 32
#define DI 64
#define NSTATE 16
#define HW 1024        // H*W

__global__ __launch_bounds__(NTHREADS, 2)
void mamba_fused_kernel(
    const float* __restrict__ x,          // [B=2, S=64, DM=32, HW=1024]
    const float* __restrict__ in_proj_w,  // [128, 32]
    const float* __restrict__ conv_w,     // [64, 1, 4]
    const float* __restrict__ conv_b,     // [64]
    const float* __restrict__ x_proj_w,   // [34, 64]
    const float* __restrict__ dt_proj_w,  // [64, 2]
    const float* __restrict__ dt_proj_b,  // [64]
    const float* __restrict__ A_log,      // [64, 16]
    const float* __restrict__ Dp,         // [64]
    const float* __restrict__ out_proj_w, // [32, 64]
    const float* __restrict__ lin1_w,     // [16, 32]
    const float* __restrict__ lin1_b,     // [16]
    const float* __restrict__ lin2_w,     // [1, 16]
    const float* __restrict__ lin2_b,     // [1]
    float* __restrict__ out)              // [B=2, S=64, HW=1024]
{
    __shared__ float xpw_r[34][68];          // x_proj_w row-major, padded (f4 conflict-free)
    __shared__ float xin_s[2][SPB][DM];      // double-buffered input slab
    __shared__ float xt_s[SPB][DI];          // conv+silu output per step
    __shared__ float dbc_s[SPB][40];         // [0:16)=B, [16:32)=C, [32],[33]=dt
    __shared__ float part_s[SPB][SEQ][2];    // per-(seq,t) warp partials of y.v
    __shared__ float wm_s[DM];
    __shared__ float v_sm[DI];
    __shared__ float c_sm;

    const int tid = threadIdx.x;
    const int j = tid >> 6;      // sequence within block (0..3)
    const int d = tid & 63;      // channel (0..63)

    // ---------------- init: stage x_proj_w into smem ----------------
    for (int idx = tid; idx < 34 * 64; idx += NTHREADS) {
        int k = idx >> 6, dd = idx & 63;
        xpw_r[k][dd] = x_proj_w[idx];
    }
    // fold head: wm[m] = sum_k lin2[k]*lin1[k,m]
    if (tid < DM) {
        float acc = 0.f;
        #pragma unroll
        for (int k = 0; k < 16; k++) acc = fmaf(lin2_w[k], lin1_w[k * 32 + tid], acc);
        wm_s[tid] = acc;
    }
    if (tid == 0) {
        float c = lin2_b[0];
        #pragma unroll
        for (int k = 0; k < 16; k++) c = fmaf(lin2_w[k], lin1_b[k], c);
        c_sm = c;
    }
    __syncthreads();
    // v[dd] = sum_m wm[m] * out_proj_w[m,dd]
    if (tid < DI) {
        float acc = 0.f;
        #pragma unroll
        for (int m = 0; m < 32; m++) acc = fmaf(wm_s[m], out_proj_w[m * 64 + tid], acc);
        v_sm[tid] = acc;
    }

    // ---------------- per-thread constants in registers ----------------
    float w_xh[32], w_z[32];
    #pragma unroll
    for (int q = 0; q < 8; q++) {
        float4 a = *(const float4*)&in_proj_w[d * 32 + q * 4];
        w_xh[q * 4 + 0] = a.x; w_xh[q * 4 + 1] = a.y;
        w_xh[q * 4 + 2] = a.z; w_xh[q * 4 + 3] = a.w;
        float4 bz = *(const float4*)&in_proj_w[(64 + d) * 32 + q * 4];
        w_z[q * 4 + 0] = bz.x; w_z[q * 4 + 1] = bz.y;
        w_z[q * 4 + 2] = bz.z; w_z[q * 4 + 3] = bz.w;
    }
    float4 cwv = *(const float4*)&conv_w[d * 4];
    const float cw0 = cwv.x, cw1 = cwv.y, cw2 = cwv.z, cw3 = cwv.w;
    const float cb = conv_b[d];
    const float dtw0 = dt_proj_w[d * 2 + 0];
    const float dtw1 = dt_proj_w[d * 2 + 1];
    const float dtb  = dt_proj_b[d];
    const float dpv  = Dp[d];
    float A_d[NSTATE];
    #pragma unroll
    for (int n = 0; n < NSTATE; n++) A_d[n] = -__expf(A_log[d * NSTATE + n]);
    float h[NSTATE];
    #pragma unroll
    for (int n = 0; n < NSTATE; n++) h[n] = 0.f;
    float xh1 = 0.f, xh2 = 0.f, xh3 = 0.f;   // conv history (t-1, t-2, t-3)

    // input loader mapping (threads 0..127): 4 consecutive hw per m -> coalesced 16B
    const int lj = tid & 3, lm = tid >> 2;   // valid for tid < 128
    const int lbb = blockIdx.x * SPB + lj;
    const int lbase = (lbb >> 10) * (SEQ * DM * HW) + (lbb & (HW - 1));
    if (tid < 128) xin_s[0][lj][lm] = x[lbase + lm * HW];

    __syncthreads();     // v_sm, xin_s[0] ready
    const float vv = v_sm[d];

    // ---------------- main time loop ----------------
    for (int t = 0; t < SEQ; t++) {
        const int buf = t & 1;

        // phase A: in_proj (xh, z) from registers + smem broadcast
        float xh0 = 0.f, z = 0.f;
        {
            const float4* xp4 = (const float4*)xin_s[buf][j];
            #pragma unroll
            for (int q = 0; q < 8; q++) {
                float4 xv = xp4[q];
                xh0 = fmaf(xv.x, w_xh[q * 4 + 0], xh0); z = fmaf(xv.x, w_z[q * 4 + 0], z);
                xh0 = fmaf(xv.y, w_xh[q * 4 + 1], xh0); z = fmaf(xv.y, w_z[q * 4 + 1], z);
                xh0 = fmaf(xv.z, w_xh[q * 4 + 2], xh0); z = fmaf(xv.z, w_z[q * 4 + 2], z);
                xh0 = fmaf(xv.w, w_xh[q * 4 + 3], xh0); z = fmaf(xv.w, w_z[q * 4 + 3], z);
            }
        }
        // causal depthwise conv (K=4) + SiLU
        float xc = cb;
        xc = fmaf(cw0, xh3, xc);
        xc = fmaf(cw1, xh2, xc);
        xc = fmaf(cw2, xh1, xc);
        xc = fmaf(cw3, xh0, xc);
        xh3 = xh2; xh2 = xh1; xh1 = xh0;
        const float xt = xc / (1.f + __expf(-xc));
        xt_s[j][d] = xt;
        __syncthreads();

        // phase B: x_proj dots (threads d<34), plus prefetch next input slab
        if (d < 34) {
            const float4* wp = (const float4*)xpw_r[d];
            const float4* xp = (const float4*)xt_s[j];
            float a0 = 0.f, a1 = 0.f, a2 = 0.f, a3 = 0.f;
            #pragma unroll
            for (int q = 0; q < 16; q++) {
                float4 w4 = wp[q];
                float4 x4 = xp[q];
                a0 = fmaf(x4.x, w4.x, a0);
                a1 = fmaf(x4.y, w4.y, a1);
                a2 = fmaf(x4.z, w4.z, a2);
                a3 = fmaf(x4.w, w4.w, a3);
            }
            const int pos = (d < 2) ? (32 + d) : (d - 2);
            dbc_s[j][pos] = (a0 + a1) + (a2 + a3);
        }
        if (t + 1 < SEQ && tid < 128)
            xin_s[buf ^ 1][lj][lm] = x[lbase + (t + 1) * (DM * HW) + lm * HW];
        __syncthreads();

        // phase C: delta, scan update, gate, folded output dot
        const float dt0 = dbc_s[j][32];
        const float dt1 = dbc_s[j][33];
        const float dpre = fmaf(dt0, dtw0, fmaf(dt1, dtw1, dtb));
        const float delta = (dpre > 15.f) ? dpre : __logf(1.f + __expf(dpre));
        const float du = delta * xt;

        const float4* Bp = (const float4*)&dbc_s[j][0];
        const float4* Cp = (const float4*)&dbc_s[j][16];
        float y = 0.f;
        #pragma unroll
        for (int q = 0; q < 4; q++) {
            float4 B4 = Bp[q];
            float4 C4 = Cp[q];
            float dA;
            dA = __expf(delta * A_d[4 * q + 0]);
            h[4 * q + 0] = fmaf(dA, h[4 * q + 0], du * B4.x);
            y = fmaf(h[4 * q + 0], C4.x, y);
            dA = __expf(delta * A_d[4 * q + 1]);
            h[4 * q + 1] = fmaf(dA, h[4 * q + 1], du * B4.y);
            y = fmaf(h[4 * q + 1], C4.y, y);
            dA = __expf(delta * A_d[4 * q + 2]);
            h[4 * q + 2] = fmaf(dA, h[4 * q + 2], du * B4.z);
            y = fmaf(h[4 * q + 2], C4.z, y);
            dA = __expf(delta * A_d[4 * q + 3]);
            h[4 * q + 3] = fmaf(dA, h[4 * q + 3], du * B4.w);
            y = fmaf(h[4 * q + 3], C4.w, y);
        }
        y = fmaf(xt, dpv, y);                    // D * u skip
        const float sz = z / (1.f + __expf(-z)); // silu(z)
        y *= sz;

        float acc = y * vv;                      // folded head dot contribution
        #pragma unroll
        for (int off = 16; off; off >>= 1)
            acc += __shfl_xor_sync(0xffffffffu, acc, off);
        if ((d & 31) == 0) part_s[j][t][d >> 5] = acc;
    }

    __syncthreads();
    // ---------------- output: [B, S, HW], coalesced over 4 hw ----------------
    {
        const int tt = tid >> 2;
        const int jj = tid & 3;
        const float val = part_s[jj][tt][0] + part_s[jj][tt][1] + c_sm;
        const int obb = blockIdx.x * SPB + jj;
        const int ob = obb >> 10;
        const int ohw = obb & (HW - 1);
        out[ob * (SEQ * HW) + tt * HW + ohw] = val;
    }
}

extern "C" void kernel_launch(void* const* d_in, const int* in_sizes, int n_in,
                              void* d_out, int out_size) {
    const float* x         = (const float*)d_in[0];
    const float* in_proj_w = (const float*)d_in[1];
    const float* conv_w    = (const float*)d_in[2];
    const float* conv_b    = (const float*)d_in[3];
    const float* x_proj_w  = (const float*)d_in[4];
    const float* dt_proj_w = (const float*)d_in[5];
    const float* dt_proj_b = (const float*)d_in[6];
    const float* A_log     = (const float*)d_in[7];
    const float* Dp        = (const float*)d_in[8];
    const float* out_proj_w= (const float*)d_in[9];
    const float* lin1_w    = (const float*)d_in[10];
    const float* lin1_b    = (const float*)d_in[11];
    const float* lin2_w    = (const float*)d_in[12];
    const float* lin2_b    = (const float*)d_in[13];
    float* out = (float*)d_out;

    const int BB = 2048;                 // B * H * W
    dim3 grid(BB / SPB);                 // 512 blocks
    dim3 block(NTHREADS);                // 256 threads
    mamba_fused_kernel<<<grid, block>>>(
        x, in_proj_w, conv_w, conv_b, x_proj_w, dt_proj_w, dt_proj_b,
        A_log, Dp, out_proj_w, lin1_w, lin1_b, lin2_w, lin2_b, out);
}

// round 2
// speedup vs baseline: 1.0831x; 1.0831x over previous
#include <cuda_runtime.h>

typedef unsigned long long ull;

#define SEQ 64
#define DM 32
#define DI 64
#define HW 1024

// Packed f32x2 helpers (sm_103a FFMA2 — ptxas never auto-fuses these)
#define FMA2(d, a, b, c) \
    asm("fma.rn.f32x2 %0, %1, %2, %3;" : "=l"(d) : "l"(a), "l"(b), "l"(c))
#define MUL2(d, a, b) \
    asm("mul.rn.f32x2 %0, %1, %2;" : "=l"(d) : "l"(a), "l"(b))
__device__ __forceinline__ ull pack2(float lo, float hi) {
    ull r; asm("mov.b64 %0, {%1, %2};" : "=l"(r) : "f"(lo), "f"(hi)); return r;
}
__device__ __forceinline__ float2 unpack2(ull v) {
    float2 f; asm("mov.b64 {%0, %1}, %2;" : "=f"(f.x), "=f"(f.y) : "l"(v)); return f;
}

// Scratch: x transposed to [BB=2048][S=64][DM=32]
__device__ float g_xr[2 * HW * SEQ * DM];

// ---------------- transpose: x [2][64][32][1024] -> g_xr [bb][t][m] ----------------
__global__ __launch_bounds__(256) void transpose_kernel(const float* __restrict__ x) {
    __shared__ float tile[DM][65];
    const int bi = blockIdx.x;             // 2*64*16 = 2048 blocks
    const int c  = bi & 15;                // 64-wide hw chunk
    const int t  = (bi >> 4) & 63;
    const int b  = bi >> 10;
    const float* src = x + ((b * SEQ + t) * DM) * HW + c * 64;
    const int tid = threadIdx.x;
    #pragma unroll
    for (int i = 0; i < 8; i++) {
        int idx = tid + i * 256;
        int m = idx >> 6, hw = idx & 63;
        tile[m][hw] = src[m * HW + hw];
    }
    __syncthreads();
    #pragma unroll
    for (int i = 0; i < 8; i++) {
        int idx = tid + i * 256;
        int hw = idx >> 5, m = idx & 31;
        g_xr[(b * HW + c * 64 + hw) * (SEQ * DM) + t * DM + m] = tile[m][hw];
    }
}

// ---------------- fused mamba: 1 sequence = 2 warps, named-barrier coupled ----------------
__global__ __launch_bounds__(256, 2) void mamba_main(
    const float* __restrict__ in_proj_w,  // [128,32]
    const float* __restrict__ conv_w,     // [64,1,4]
    const float* __restrict__ conv_b,     // [64]
    const float* __restrict__ x_proj_w,   // [34,64]
    const float* __restrict__ dt_proj_w,  // [64,2]
    const float* __restrict__ dt_proj_b,  // [64]
    const float* __restrict__ A_log,      // [64,16]
    const float* __restrict__ Dp,         // [64]
    const float* __restrict__ out_proj_w, // [32,64]
    const float* __restrict__ lin1_w,     // [16,32]
    const float* __restrict__ lin1_b,     // [16]
    const float* __restrict__ lin2_w,     // [1,16]
    const float* __restrict__ lin2_b,     // [1]
    float* __restrict__ out)              // [2,64,1024]
{
    __shared__ float xpw_s[34][66];       // padded: (row*33 + q8) mod 32 distinct -> conflict-free LDS.64
    __shared__ float xin_s[2][4][DM];     // double-buffered input slab per seq
    __shared__ float xt_s[2][4][DI];      // double-buffered conv output per seq
    __shared__ float dbc_s[4][2][32];     // per-warp private copy: [0:16)=B, [16:32)=C
    __shared__ float part_s[4][SEQ][2];
    __shared__ float wm_s[DM];
    __shared__ float v_sm[DI];
    __shared__ float a_s[DI][18];         // general-A fallback
    __shared__ float c_sm;
    __shared__ int slow_s;

    const int tid = threadIdx.x;
    const int j = tid >> 6;               // sequence in block (0..3)
    const int d = tid & 63;               // channel
    const int w = (tid >> 5) & 1;         // warp within sequence
    const int l = tid & 31;               // lane

    if (tid == 0) slow_s = 0;
    for (int idx = tid; idx < 34 * 64; idx += 256)
        xpw_s[idx >> 6][idx & 63] = x_proj_w[idx];
    if (tid < DM) {
        float acc = 0.f;
        #pragma unroll
        for (int k = 0; k < 16; k++) acc = fmaf(lin2_w[k], lin1_w[k * 32 + tid], acc);
        wm_s[tid] = acc;
    }
    if (tid == 0) {
        float c = lin2_b[0];
        #pragma unroll
        for (int k = 0; k < 16; k++) c = fmaf(lin2_w[k], lin1_b[k], c);
        c_sm = c;
    }
    __syncthreads();
    if (tid < DI) {
        float acc = 0.f;
        #pragma unroll
        for (int m = 0; m < 32; m++) acc = fmaf(wm_s[m], out_proj_w[m * 64 + tid], acc);
        v_sm[tid] = acc;
        // A structure check: A[d][n] == -(n+1) ? (true for this dataset; fallback otherwise)
        int bad = 0;
        #pragma unroll
        for (int n = 0; n < 16; n++) {
            float a = -__expf(A_log[tid * 16 + n]);
            a_s[tid][n] = a;
            if (fabsf(a + (float)(n + 1)) > 1e-4f * (float)(n + 1)) bad = 1;
        }
        if (bad) atomicOr(&slow_s, 1);
    }

    // per-thread constants (in_proj weights packed as f32x2 pairs -> registers)
    ull wxh[16], wz[16];
    {
        const ull* p  = (const ull*)(in_proj_w + d * DM);
        const ull* pz = (const ull*)(in_proj_w + (DI + d) * DM);
        #pragma unroll
        for (int q = 0; q < 16; q++) { wxh[q] = p[q]; wz[q] = pz[q]; }
    }
    const float4 cw = *(const float4*)(conv_w + d * 4);
    const float cb = conv_b[d];
    const float2 dtw = *(const float2*)(dt_proj_w + d * 2);
    const float dtb = dt_proj_b[d];
    const float dpv = Dp[d];

    const int bb = blockIdx.x * 4 + j;
    const float* xbase = g_xr + bb * (SEQ * DM);
    if (w == 0 && l < 8)
        *(float4*)&xin_s[0][j][l * 4] = *(const float4*)(xbase + l * 4);
    __syncthreads();
    const float vv = v_sm[d];
    const int slow = slow_s;

    ull h2[8];
    #pragma unroll
    for (int q = 0; q < 8; q++) h2[q] = 0ull;
    float xm1 = 0.f, xm2 = 0.f, xm3 = 0.f;   // conv history

    for (int t = 0; t < SEQ; t++) {
        const int buf = t & 1;

        // ---- phase A: in_proj (packed FMA2, register weights), conv, SiLU ----
        ull accx = 0ull, accz = 0ull;
        const ull* xp = (const ull*)xin_s[buf][j];
        #pragma unroll
        for (int q = 0; q < 16; q++) {
            ull xv = xp[q];
            FMA2(accx, wxh[q], xv, accx);
            FMA2(accz, wz[q], xv, accz);
        }
        float2 fx = unpack2(accx), fz = unpack2(accz);
        const float xh0 = fx.x + fx.y;
        const float z = fz.x + fz.y;
        float xc = cb;
        xc = fmaf(cw.x, xm3, xc);
        xc = fmaf(cw.y, xm2, xc);
        xc = fmaf(cw.z, xm1, xc);
        xc = fmaf(cw.w, xh0, xc);
        xm3 = xm2; xm2 = xm1; xm1 = xh0;
        const float xt = __fdividef(xc, 1.f + __expf(-xc));
        xt_s[buf][j][d] = xt;

        // prefetch next input slab (warp-even, one 128B line)
        if (w == 0 && l < 8 && t + 1 < SEQ)
            *(float4*)&xin_s[buf ^ 1][j][l * 4] =
                *(const float4*)(xbase + (t + 1) * DM + l * 4);

        asm volatile("bar.sync %0, 64;" :: "r"(j + 1) : "memory");

        // ---- phase B: x_proj — lane l computes row l+2 (B/C), dt via butterfly ----
        {
            const ull* wr  = (const ull*)xpw_s[l + 2];
            const ull* xtp = (const ull*)xt_s[buf][j];
            ull acc = 0ull;
            #pragma unroll
            for (int q = 0; q < 32; q++) FMA2(acc, wr[q], xtp[q], acc);
            float2 a2 = unpack2(acc);
            dbc_s[j][w][l] = a2.x + a2.y;
        }
        const float2 xtl = *(const float2*)&xt_s[buf][j][2 * l];
        const float2 w0 = *(const float2*)&xpw_s[0][2 * l];
        const float2 w1 = *(const float2*)&xpw_s[1][2 * l];
        float u0 = fmaf(w0.y, xtl.y, w0.x * xtl.x);
        float u1 = fmaf(w1.y, xtl.y, w1.x * xtl.x);
        #pragma unroll
        for (int off = 16; off; off >>= 1) {
            u0 += __shfl_xor_sync(0xffffffffu, u0, off);
            u1 += __shfl_xor_sync(0xffffffffu, u1, off);
        }
        __syncwarp();

        // ---- phase C: delta, scan (packed, power-chain dA), gate, folded head ----
        const float dpre = fmaf(dtw.x, u0, fmaf(dtw.y, u1, dtb));
        const float delta = dpre > 15.f ? dpre : __logf(1.f + __expf(dpre));
        const float du = delta * xt;
        const ull du2 = pack2(du, du);
        ull y2 = 0ull;
        const float* db = dbc_s[j][w];
        if (!slow) {
            const float r = __expf(-delta);
            const float rr = r * r;
            ull cur = pack2(r, rr);            // (r^1, r^2)
            const ull rrd = pack2(rr, rr);
            #pragma unroll
            for (int q = 0; q < 8; q++) {
                ull bp = *(const ull*)&db[2 * q];
                ull cp = *(const ull*)&db[16 + 2 * q];
                ull tmp;
                MUL2(tmp, bp, du2);
                FMA2(h2[q], cur, h2[q], tmp);
                FMA2(y2, h2[q], cp, y2);
                if (q < 7) MUL2(cur, cur, rrd);
            }
        } else {
            #pragma unroll
            for (int q = 0; q < 8; q++) {
                float2 ap = *(const float2*)&a_s[d][2 * q];
                ull dA = pack2(__expf(delta * ap.x), __expf(delta * ap.y));
                ull bp = *(const ull*)&db[2 * q];
                ull cp = *(const ull*)&db[16 + 2 * q];
                ull tmp;
                MUL2(tmp, bp, du2);
                FMA2(h2[q], dA, h2[q], tmp);
                FMA2(y2, h2[q], cp, y2);
            }
        }
        float2 yp = unpack2(y2);
        float y = yp.x + yp.y;
        y = fmaf(xt, dpv, y);
        y *= __fdividef(z, 1.f + __expf(-z));

        float acc = y * vv;
        #pragma unroll
        for (int off = 16; off; off >>= 1) acc += __shfl_xor_sync(0xffffffffu, acc, off);
        if (l == 0) part_s[j][t][w] = acc;
        __syncwarp();
    }

    __syncthreads();
    {
        const int tt = tid >> 2;
        const int jj = tid & 3;
        const float val = part_s[jj][tt][0] + part_s[jj][tt][1] + c_sm;
        const int obb = blockIdx.x * 4 + jj;
        out[(obb >> 10) * (SEQ * HW) + tt * HW + (obb & (HW - 1))] = val;
    }
}

extern "C" void kernel_launch(void* const* d_in, const int* in_sizes, int n_in,
                              void* d_out, int out_size) {
    const float* x         = (const float*)d_in[0];
    const float* in_proj_w = (const float*)d_in[1];
    const float* conv_w    = (const float*)d_in[2];
    const float* conv_b    = (const float*)d_in[3];
    const float* x_proj_w  = (const float*)d_in[4];
    const float* dt_proj_w = (const float*)d_in[5];
    const float* dt_proj_b = (const float*)d_in[6];
    const float* A_log     = (const float*)d_in[7];
    const float* Dp        = (const float*)d_in[8];
    const float* out_proj_w= (const float*)d_in[9];
    const float* lin1_w    = (const float*)d_in[10];
    const float* lin1_b    = (const float*)d_in[11];
    const float* lin2_w    = (const float*)d_in[12];
    const float* lin2_b    = (const float*)d_in[13];
    float* out = (float*)d_out;

    transpose_kernel<<<2048, 256>>>(x);
    mamba_main<<<512, 256>>>(in_proj_w, conv_w, conv_b, x_proj_w,
                             dt_proj_w, dt_proj_b, A_log, Dp, out_proj_w,
                             lin1_w, lin1_b, lin2_w, lin2_b, out);
}